// round 11
// baseline (speedup 1.0000x reference)
#include <cuda_runtime.h>
#include <cuda_bf16.h>
#include <cuda_fp16.h>
#include <mma.h>
#include <cstdint>

using namespace nvcuda;

static constexpr int BATCH = 4;
static constexpr int NTOK  = 4096;   // H*W
static constexpr int CH    = 512;
static constexpr int FGD   = 64;

static constexpr long long O_ELEMS = (long long)BATCH * NTOK * CH;    // 8388608
static constexpr long long B_ELEMS = (long long)BATCH * NTOK * NTOK;  // 67108864

// ---------------- scratch (static __device__ -- no allocations allowed) ----------
__device__ float  d_f[(size_t)BATCH * NTOK * FGD];
__device__ float  d_g[(size_t)BATCH * NTOK * FGD];
__device__ __half d_h16[(size_t)BATCH * NTOK * CH];          // h in fp16 (h >= 0)
__device__ __half d_betah[(size_t)BATCH * NTOK * NTOK];      // beta in fp16
__device__ float  d_oatt[(size_t)BATCH * NTOK * CH];
__device__ float  d_rowm[BATCH * NTOK];
__device__ float  d_rowl[BATCH * NTOK];
__device__ float  d_beta_scratch[(size_t)BATCH * NTOK * NTOK]; // only if harness wants o-only

// ---------------- bf16 split helper (x = hi + lo, ~17-bit effective mantissa) ----
__device__ __forceinline__ void split4(const float4 v, __nv_bfloat16* hi, __nv_bfloat16* lo) {
    hi[0] = __float2bfloat16(v.x); lo[0] = __float2bfloat16(v.x - __bfloat162float(hi[0]));
    hi[1] = __float2bfloat16(v.y); lo[1] = __float2bfloat16(v.y - __bfloat162float(hi[1]));
    hi[2] = __float2bfloat16(v.z); lo[2] = __float2bfloat16(v.z - __bfloat162float(hi[2]));
    hi[3] = __float2bfloat16(v.w); lo[3] = __float2bfloat16(v.w - __bfloat162float(hi[3]));
}

// ---------------- cp.async helpers (Ampere path, valid on sm_103) ----------------
__device__ __forceinline__ uint32_t smem_u32(const void* p) {
    uint32_t a;
    asm("{ .reg .u64 t; cvta.to.shared.u64 t, %1; cvt.u32.u64 %0, t; }" : "=r"(a) : "l"(p));
    return a;
}
__device__ __forceinline__ void cp_async16(uint32_t dst, const void* src) {
    asm volatile("cp.async.cg.shared.global [%0], [%1], 16;" :: "r"(dst), "l"(src));
}
__device__ __forceinline__ void cp_commit() {
    asm volatile("cp.async.commit_group;");
}
template <int N>
__device__ __forceinline__ void cp_wait() {
    asm volatile("cp.async.wait_group %0;" :: "n"(N));
}

// ================== generic GEMM v2: C = act(A[M,K] @ B[K,N] + bias) ==============
// bf16-split 3-mma scheme. Register-prefetch + double-buffered smem, one sync per
// k-chunk. 128x64 tile, 8 warps, acc[2][2]. M%128==0, N%64==0, K%32==0.
static constexpr int GBM = 128, GBN = 64, GBK = 32;
static constexpr int ALD = GBK + 8;   // 40
static constexpr int BLD = GBN + 8;   // 72
static constexpr int CLD = GBN + 4;   // 68
static constexpr int G_AHALF = GBM * ALD;              // 5120
static constexpr int G_BHALF = GBK * BLD;              // 2304
static constexpr int G_STAGE = 2 * G_AHALF + 2 * G_BHALF;   // 14848 bf16
static constexpr int GEMM_SMEM = 2 * G_STAGE * 2;      // 59392 B

__global__ void __launch_bounds__(256)
gemm_split_kernel(const float* __restrict__ A, const float* __restrict__ B,
                  const float* __restrict__ bias, float* __restrict__ C,
                  __half* __restrict__ C16,
                  int K, int N, int relu)
{
    extern __shared__ __align__(16) unsigned char gsm[];
    float* Csm = reinterpret_cast<float*>(gsm);

    const int m0  = blockIdx.y * GBM;
    const int n0  = blockIdx.x * GBN;
    const int tid = threadIdx.x;
    const int wid = tid >> 5;
    const int wm  = wid >> 1;
    const int wn  = wid & 1;

    wmma::fragment<wmma::accumulator, 16, 16, 16, float> acc[2][2];
    #pragma unroll
    for (int i = 0; i < 2; i++)
        #pragma unroll
        for (int j = 0; j < 2; j++)
            wmma::fill_fragment(acc[i][j], 0.0f);

    const int NCHUNK = K >> 5;
    float4 ra[4], rb[2];

    #pragma unroll
    for (int i = 0; i < 4; i++) {
        int idx = tid + i * 256;
        int row = idx >> 3;
        int c4  = (idx & 7) << 2;
        ra[i] = *reinterpret_cast<const float4*>(A + (long long)(m0 + row) * K + c4);
    }
    #pragma unroll
    for (int i = 0; i < 2; i++) {
        int idx = tid + i * 256;
        int row = idx >> 4;
        int c4  = (idx & 15) << 2;
        rb[i] = *reinterpret_cast<const float4*>(B + (long long)row * N + n0 + c4);
    }

    #pragma unroll 1
    for (int c = 0; c < NCHUNK; c++) {
        __nv_bfloat16* stage = reinterpret_cast<__nv_bfloat16*>(gsm) + (c & 1) * G_STAGE;
        __nv_bfloat16* Ahi = stage;
        __nv_bfloat16* Alo = Ahi + G_AHALF;
        __nv_bfloat16* Bhi = Alo + G_AHALF;
        __nv_bfloat16* Blo = Bhi + G_BHALF;

        #pragma unroll
        for (int i = 0; i < 4; i++) {
            int idx = tid + i * 256;
            int row = idx >> 3;
            int c4  = (idx & 7) << 2;
            split4(ra[i], &Ahi[row * ALD + c4], &Alo[row * ALD + c4]);
        }
        #pragma unroll
        for (int i = 0; i < 2; i++) {
            int idx = tid + i * 256;
            int row = idx >> 4;
            int c4  = (idx & 15) << 2;
            split4(rb[i], &Bhi[row * BLD + c4], &Blo[row * BLD + c4]);
        }
        __syncthreads();

        if (c + 1 < NCHUNK) {
            const long long k0 = (long long)(c + 1) << 5;
            #pragma unroll
            for (int i = 0; i < 4; i++) {
                int idx = tid + i * 256;
                int row = idx >> 3;
                int c4  = (idx & 7) << 2;
                ra[i] = *reinterpret_cast<const float4*>(A + (long long)(m0 + row) * K + k0 + c4);
            }
            #pragma unroll
            for (int i = 0; i < 2; i++) {
                int idx = tid + i * 256;
                int row = idx >> 4;
                int c4  = (idx & 15) << 2;
                rb[i] = *reinterpret_cast<const float4*>(B + (k0 + row) * N + n0 + c4);
            }
        }

        #pragma unroll
        for (int ks = 0; ks < 2; ks++) {
            wmma::fragment<wmma::matrix_a, 16, 16, 16, __nv_bfloat16, wmma::row_major> ah[2], al[2];
            wmma::fragment<wmma::matrix_b, 16, 16, 16, __nv_bfloat16, wmma::row_major> bh[2], bl[2];
            #pragma unroll
            for (int r2 = 0; r2 < 2; r2++) {
                wmma::load_matrix_sync(ah[r2], &Ahi[(wm * 32 + r2 * 16) * ALD + ks * 16], ALD);
                wmma::load_matrix_sync(al[r2], &Alo[(wm * 32 + r2 * 16) * ALD + ks * 16], ALD);
            }
            #pragma unroll
            for (int cn = 0; cn < 2; cn++) {
                wmma::load_matrix_sync(bh[cn], &Bhi[(ks * 16) * BLD + wn * 32 + cn * 16], BLD);
                wmma::load_matrix_sync(bl[cn], &Blo[(ks * 16) * BLD + wn * 32 + cn * 16], BLD);
            }
            #pragma unroll
            for (int r2 = 0; r2 < 2; r2++)
                #pragma unroll
                for (int cn = 0; cn < 2; cn++) {
                    wmma::mma_sync(acc[r2][cn], ah[r2], bh[cn], acc[r2][cn]);
                    wmma::mma_sync(acc[r2][cn], ah[r2], bl[cn], acc[r2][cn]);
                    wmma::mma_sync(acc[r2][cn], al[r2], bh[cn], acc[r2][cn]);
                }
        }
    }

    __syncthreads();
    #pragma unroll
    for (int r2 = 0; r2 < 2; r2++)
        #pragma unroll
        for (int cn = 0; cn < 2; cn++)
            wmma::store_matrix_sync(&Csm[(wm * 32 + r2 * 16) * CLD + wn * 32 + cn * 16],
                                    acc[r2][cn], CLD, wmma::mem_row_major);
    __syncthreads();

    #pragma unroll
    for (int i = 0; i < 8; i++) {
        int idx = tid + i * 256;
        int row = idx >> 4;
        int c4  = (idx & 15) << 2;
        float4 v = *reinterpret_cast<const float4*>(&Csm[row * CLD + c4]);
        if (bias != nullptr) {
            float4 bv = *reinterpret_cast<const float4*>(bias + n0 + c4);
            v.x += bv.x; v.y += bv.y; v.z += bv.z; v.w += bv.w;
        }
        if (relu) {
            v.x = fmaxf(v.x, 0.f); v.y = fmaxf(v.y, 0.f);
            v.z = fmaxf(v.z, 0.f); v.w = fmaxf(v.w, 0.f);
        }
        if (C16 != nullptr) {
            __half2 h01 = __floats2half2_rn(v.x, v.y);
            __half2 h23 = __floats2half2_rn(v.z, v.w);
            uint2 p;
            p.x = *reinterpret_cast<uint32_t*>(&h01);
            p.y = *reinterpret_cast<uint32_t*>(&h23);
            *reinterpret_cast<uint2*>(C16 + (long long)(m0 + row) * N + n0 + c4) = p;
        } else {
            *reinterpret_cast<float4*>(C + (long long)(m0 + row) * N + n0 + c4) = v;
        }
    }
}

// ================== PV GEMM v5: 128x128 tile, 256 thr, acc[2][4], cp.async =======
// Halves beta re-reads vs the 128x64 tile (4 n-tiles instead of 8). KC=32,
// 2-stage cp.async double buffer, ~37.9 KB smem, no prefetch registers.
static constexpr int P5_ALD  = 40;    // 32 + 8 halves (80 B rows, 16B-mult)
static constexpr int P5_BLD  = 136;   // 128 + 8 halves (272 B rows, 16B-mult)
static constexpr int P5_ABUF = 128 * P5_ALD;          // 5120 halves
static constexpr int P5_BBUF = 32 * P5_BLD;           // 4352 halves
static constexpr int P5_STAGE = P5_ABUF + P5_BBUF;    // 9472 halves
static constexpr int P5_SMEM  = 2 * P5_STAGE * 2;     // 37888 B
static constexpr int P5_NCHUNK = NTOK / 32;           // 128

__global__ void __launch_bounds__(256)
pv_f16s_kernel(const __half* __restrict__ betah, const __half* __restrict__ h16,
               float* __restrict__ oatt)
{
    extern __shared__ __align__(16) __half pvsm[];

    const __half* A = betah + (long long)blockIdx.z * NTOK * NTOK;
    const __half* B = h16   + (long long)blockIdx.z * NTOK * CH;
    float*        C = oatt  + (long long)blockIdx.z * NTOK * CH;
    const int m0  = blockIdx.y * 128;
    const int n0  = blockIdx.x * 128;
    const int tid = threadIdx.x;
    const int wid = tid >> 5;
    const int wm  = wid >> 1;  // 0..3 -> rows 32*wm
    const int wn  = wid & 1;   // 0..1 -> cols 64*wn

    const uint32_t smbase = smem_u32(pvsm);

    auto issue_chunk = [&](int c) {
        const int buf = c & 1;
        uint32_t sa = smbase + (uint32_t)(buf * P5_STAGE) * 2;
        uint32_t sb = sa + (uint32_t)P5_ABUF * 2;
        const long long k0 = (long long)c * 32;
        // A: 128 rows x 32 halves = 512 x 8-halves(16B); 256 thr -> 2 each
        #pragma unroll
        for (int i = 0; i < 2; i++) {
            int idx = tid + i * 256;         // 0..511
            int row = idx >> 2;              // 0..127
            int c8  = (idx & 3) << 3;        // 0,8,16,24 halves
            cp_async16(sa + (uint32_t)(row * P5_ALD + c8) * 2,
                       A + (long long)(m0 + row) * NTOK + k0 + c8);
        }
        // B: 32 rows x 128 halves = 512 x 8-halves; 256 thr -> 2 each
        #pragma unroll
        for (int i = 0; i < 2; i++) {
            int idx = tid + i * 256;         // 0..511
            int row = idx >> 4;              // 0..31
            int c8  = (idx & 15) << 3;       // 0..120 halves
            cp_async16(sb + (uint32_t)(row * P5_BLD + c8) * 2,
                       B + (long long)(k0 + row) * CH + n0 + c8);
        }
        cp_commit();
    };

    wmma::fragment<wmma::accumulator, 16, 16, 16, float> acc[2][4];
    #pragma unroll
    for (int i = 0; i < 2; i++)
        #pragma unroll
        for (int j = 0; j < 4; j++)
            wmma::fill_fragment(acc[i][j], 0.0f);

    issue_chunk(0);

    #pragma unroll 1
    for (int c = 0; c < P5_NCHUNK; c++) {
        if (c + 1 < P5_NCHUNK) {
            issue_chunk(c + 1);
            cp_wait<1>();     // chunk c landed (c+1 may still fly)
        } else {
            cp_wait<0>();
        }
        __syncthreads();

        const __half* Af = pvsm + (c & 1) * P5_STAGE;
        const __half* Bf = Af + P5_ABUF;
        #pragma unroll
        for (int ks = 0; ks < 2; ks++) {
            wmma::fragment<wmma::matrix_a, 16, 16, 16, __half, wmma::row_major> af[2];
            #pragma unroll
            for (int r2 = 0; r2 < 2; r2++)
                wmma::load_matrix_sync(af[r2], &Af[(wm * 32 + r2 * 16) * P5_ALD + ks * 16], P5_ALD);
            #pragma unroll
            for (int j = 0; j < 4; j++) {
                wmma::fragment<wmma::matrix_b, 16, 16, 16, __half, wmma::row_major> bf;
                wmma::load_matrix_sync(bf, &Bf[(ks * 16) * P5_BLD + wn * 64 + j * 16], P5_BLD);
                #pragma unroll
                for (int r2 = 0; r2 < 2; r2++)
                    wmma::mma_sync(acc[r2][j], af[r2], bf, acc[r2][j]);
            }
        }
        __syncthreads();   // all warps done with buf before next issue overwrites it
    }

    // direct gmem epilogue (no bias/relu)
    #pragma unroll
    for (int r2 = 0; r2 < 2; r2++)
        #pragma unroll
        for (int j = 0; j < 4; j++)
            wmma::store_matrix_sync(C + (long long)(m0 + wm * 32 + r2 * 16) * CH + n0 + wn * 64 + j * 16,
                                    acc[r2][j], CH, wmma::mem_row_major);
}

// ================== scores: raw S = g @ f^T streamed out + online row max/sum ====
static constexpr int SLD = 132;
static constexpr int GLD = 72;
static constexpr int SCORES_SMEM = 4 * 128 * GLD * 2 + 128 * SLD * 4; // 141312 B

__global__ void __launch_bounds__(512)
scores_kernel(const float* __restrict__ g, const float* __restrict__ f,
              float* __restrict__ sraw, float* __restrict__ rowm, float* __restrict__ rowl)
{
    extern __shared__ unsigned char smraw[];
    __nv_bfloat16* Ghi = reinterpret_cast<__nv_bfloat16*>(smraw);
    __nv_bfloat16* Glo = Ghi + 128 * GLD;
    __nv_bfloat16* Fhi = Glo + 128 * GLD;
    __nv_bfloat16* Flo = Fhi + 128 * GLD;
    float*         S   = reinterpret_cast<float*>(Flo + 128 * GLD);

    const int b   = blockIdx.y;
    const int r0  = blockIdx.x * 128;
    const int tid = threadIdx.x;
    const int wid = tid >> 5;
    const int wm  = wid >> 2;
    const int wn  = wid & 3;

    const float* gbase = g + ((long long)b * NTOK + r0) * FGD;
    const float* fbase = f + (long long)b * NTOK * FGD;

    #pragma unroll
    for (int i = 0; i < 4; i++) {
        int idx = tid + i * 512;
        int row = idx >> 4;
        int c4  = (idx & 15) << 2;
        float4 v = *reinterpret_cast<const float4*>(gbase + row * FGD + c4);
        split4(v, &Ghi[row * GLD + c4], &Glo[row * GLD + c4]);
    }

    float m_run = -1e30f, l_run = 0.0f;
    const int srow = tid >> 2;
    const int q    = tid & 3;
    const float4* Sscan4 = reinterpret_cast<const float4*>(&S[srow * SLD + q * 32]);

    for (int ci = 0; ci < 32; ci++) {
        __syncthreads();
        #pragma unroll
        for (int i = 0; i < 4; i++) {
            int idx = tid + i * 512;
            int row = idx >> 4;
            int c4  = (idx & 15) << 2;
            float4 v = *reinterpret_cast<const float4*>(fbase + (long long)(ci * 128 + row) * FGD + c4);
            split4(v, &Fhi[row * GLD + c4], &Flo[row * GLD + c4]);
        }
        __syncthreads();

        wmma::fragment<wmma::accumulator, 16, 16, 16, float> acc[2][2];
        #pragma unroll
        for (int i = 0; i < 2; i++)
            #pragma unroll
            for (int j = 0; j < 2; j++)
                wmma::fill_fragment(acc[i][j], 0.0f);

        #pragma unroll
        for (int ks = 0; ks < 4; ks++) {
            wmma::fragment<wmma::matrix_a, 16, 16, 16, __nv_bfloat16, wmma::row_major> ah[2], al[2];
            wmma::fragment<wmma::matrix_b, 16, 16, 16, __nv_bfloat16, wmma::col_major> bh[2], bl[2];
            #pragma unroll
            for (int r2 = 0; r2 < 2; r2++) {
                wmma::load_matrix_sync(ah[r2], &Ghi[(wm * 32 + r2 * 16) * GLD + ks * 16], GLD);
                wmma::load_matrix_sync(al[r2], &Glo[(wm * 32 + r2 * 16) * GLD + ks * 16], GLD);
            }
            #pragma unroll
            for (int cn = 0; cn < 2; cn++) {
                wmma::load_matrix_sync(bh[cn], &Fhi[(wn * 32 + cn * 16) * GLD + ks * 16], GLD);
                wmma::load_matrix_sync(bl[cn], &Flo[(wn * 32 + cn * 16) * GLD + ks * 16], GLD);
            }
            #pragma unroll
            for (int r2 = 0; r2 < 2; r2++)
                #pragma unroll
                for (int cn = 0; cn < 2; cn++) {
                    wmma::mma_sync(acc[r2][cn], ah[r2], bh[cn], acc[r2][cn]);
                    wmma::mma_sync(acc[r2][cn], ah[r2], bl[cn], acc[r2][cn]);
                    wmma::mma_sync(acc[r2][cn], al[r2], bh[cn], acc[r2][cn]);
                }
        }
        #pragma unroll
        for (int r2 = 0; r2 < 2; r2++)
            #pragma unroll
            for (int cn = 0; cn < 2; cn++)
                wmma::store_matrix_sync(&S[(wm * 32 + r2 * 16) * SLD + wn * 32 + cn * 16],
                                        acc[r2][cn], SLD, wmma::mem_row_major);
        __syncthreads();

        size_t gout = (size_t)(b * NTOK + r0) * NTOK + (size_t)ci * 128;
        #pragma unroll
        for (int i = 0; i < 8; i++) {
            int idx = tid + i * 512;
            int row = idx >> 5;
            int c4  = (idx & 31) << 2;
            float4 v = *reinterpret_cast<const float4*>(&S[row * SLD + c4]);
            *reinterpret_cast<float4*>(sraw + gout + (size_t)row * NTOK + c4) = v;
        }
        float vmax = -1e30f;
        #pragma unroll
        for (int j = 0; j < 8; j++) {
            float4 a = Sscan4[j];
            vmax = fmaxf(vmax, fmaxf(fmaxf(a.x, a.y), fmaxf(a.z, a.w)));
        }
        float mn = fmaxf(m_run, vmax);
        float add = 0.0f;
        #pragma unroll
        for (int j = 0; j < 8; j++) {
            float4 a = Sscan4[j];
            add += __expf(a.x - mn) + __expf(a.y - mn) + __expf(a.z - mn) + __expf(a.w - mn);
        }
        l_run = l_run * __expf(m_run - mn) + add;
        m_run = mn;
    }

    #pragma unroll
    for (int off = 1; off < 4; off <<= 1) {
        float mo  = __shfl_xor_sync(0xffffffffu, m_run, off);
        float lo2 = __shfl_xor_sync(0xffffffffu, l_run, off);
        float mn  = fmaxf(m_run, mo);
        l_run = l_run * __expf(m_run - mn) + lo2 * __expf(mo - mn);
        m_run = mn;
    }
    if (q == 0) {
        rowm[b * NTOK + r0 + srow] = m_run;
        rowl[b * NTOK + r0 + srow] = l_run;
    }
}

// ============ normalize: beta = exp(s - m)/l  (fp32 out + fp16 copy) =============
__global__ void __launch_bounds__(256)
normalize_kernel(float* __restrict__ beta, __half* __restrict__ betah,
                 const float* __restrict__ rowm, const float* __restrict__ rowl)
{
    long long idx = (long long)blockIdx.x * 256 + threadIdx.x;
    if (idx >= (B_ELEMS >> 2)) return;
    int rowg = (int)(idx >> 10);
    float m   = __ldg(rowm + rowg);
    float inv = 1.0f / __ldg(rowl + rowg);
    float4 v = *reinterpret_cast<float4*>(beta + idx * 4);
    v.x = __expf(v.x - m) * inv;
    v.y = __expf(v.y - m) * inv;
    v.z = __expf(v.z - m) * inv;
    v.w = __expf(v.w - m) * inv;
    *reinterpret_cast<float4*>(beta + idx * 4) = v;
    __half2 h01 = __floats2half2_rn(v.x, v.y);
    __half2 h23 = __floats2half2_rn(v.z, v.w);
    uint2 p;
    p.x = *reinterpret_cast<uint32_t*>(&h01);
    p.y = *reinterpret_cast<uint32_t*>(&h23);
    *reinterpret_cast<uint2*>(betah + idx * 4) = p;
}

// ================== launch ========================================================
extern "C" void kernel_launch(void* const* d_in, const int* in_sizes, int n_in,
                              void* d_out, int out_size)
{
    (void)in_sizes; (void)n_in;
    const float* l  = (const float*)d_in[0];
    const float* r  = (const float*)d_in[1];
    const float* Wf = (const float*)d_in[2];
    const float* Wg = (const float*)d_in[3];
    const float* Wh = (const float*)d_in[4];
    const float* Wo = (const float*)d_in[5];
    const float* bf = (const float*)d_in[6];
    const float* bg = (const float*)d_in[7];
    const float* bh = (const float*)d_in[8];
    const float* bo = (const float*)d_in[9];
    float* out = (float*)d_out;

    float  *p_f, *p_g, *p_oatt, *p_rowm, *p_rowl, *p_bscr;
    __half *p_h16, *p_betah;
    cudaGetSymbolAddress((void**)&p_f,     d_f);
    cudaGetSymbolAddress((void**)&p_g,     d_g);
    cudaGetSymbolAddress((void**)&p_h16,   d_h16);
    cudaGetSymbolAddress((void**)&p_betah, d_betah);
    cudaGetSymbolAddress((void**)&p_oatt,  d_oatt);
    cudaGetSymbolAddress((void**)&p_rowm,  d_rowm);
    cudaGetSymbolAddress((void**)&p_rowl,  d_rowl);
    cudaGetSymbolAddress((void**)&p_bscr,  d_beta_scratch);

    // output layout: reference returns (o, beta) -> o first, then beta
    float* o_out    = nullptr;
    float* beta_out = nullptr;
    long long osz = (long long)out_size;
    if (osz >= O_ELEMS + B_ELEMS) { o_out = out; beta_out = out + O_ELEMS; }
    else if (osz == B_ELEMS)      { beta_out = out; }
    else                          { o_out = out; beta_out = p_bscr; }

    // one-time setup (first call is the non-captured correctness run)
    static cudaStream_t s_main = nullptr, s_side = nullptr, s_aux = nullptr;
    static cudaEvent_t  ev_root = nullptr, ev_side = nullptr, ev_aux = nullptr, ev_main = nullptr;
    if (s_main == nullptr) {
        cudaStreamCreateWithFlags(&s_main, cudaStreamNonBlocking);
        cudaStreamCreateWithFlags(&s_side, cudaStreamNonBlocking);
        cudaStreamCreateWithFlags(&s_aux,  cudaStreamNonBlocking);
        cudaEventCreateWithFlags(&ev_root, cudaEventDisableTiming);
        cudaEventCreateWithFlags(&ev_side, cudaEventDisableTiming);
        cudaEventCreateWithFlags(&ev_aux,  cudaEventDisableTiming);
        cudaEventCreateWithFlags(&ev_main, cudaEventDisableTiming);
        cudaFuncSetAttribute(scores_kernel, cudaFuncAttributeMaxDynamicSharedMemorySize, SCORES_SMEM);
        cudaFuncSetAttribute(pv_f16s_kernel, cudaFuncAttributeMaxDynamicSharedMemorySize, P5_SMEM);
        cudaFuncSetAttribute(gemm_split_kernel, cudaFuncAttributeMaxDynamicSharedMemorySize, GEMM_SMEM);
    }

    // fork from the capture (default) stream
    cudaEventRecord(ev_root, 0);
    cudaStreamWaitEvent(s_main, ev_root, 0);
    cudaStreamWaitEvent(s_side, ev_root, 0);
    cudaStreamWaitEvent(s_aux,  ev_root, 0);

    // side stream: h = relu(l @ Wh + bh) as fp16 (only needed by PV)
    gemm_split_kernel<<<dim3(8, 128, 1), 256, GEMM_SMEM, s_side>>>(l, Wh, bh, nullptr, p_h16, 512, 512, 1);
    cudaEventRecord(ev_side, s_side);

    // aux stream: f ; main stream: g  (run concurrently, both feed scores)
    gemm_split_kernel<<<dim3(1, 128, 1), 256, GEMM_SMEM, s_aux>>>(l, Wf, bf, p_f, nullptr, 512, 64, 1);
    cudaEventRecord(ev_aux, s_aux);
    gemm_split_kernel<<<dim3(1, 128, 1), 256, GEMM_SMEM, s_main>>>(r, Wg, bg, p_g, nullptr, 512, 64, 1);
    cudaStreamWaitEvent(s_main, ev_aux, 0);

    // main: scores -> normalize
    scores_kernel<<<dim3(32, 4, 1), 512, SCORES_SMEM, s_main>>>(p_g, p_f, beta_out, p_rowm, p_rowl);
    normalize_kernel<<<65536, 256, 0, s_main>>>(beta_out, p_betah, p_rowm, p_rowl);

    // join h before PV
    cudaStreamWaitEvent(s_main, ev_side, 0);
    if (o_out) {
        // o_att = beta @ h  (per batch) -- 128x128 cp.async PV
        pv_f16s_kernel<<<dim3(4, 32, 4), 256, P5_SMEM, s_main>>>(p_betah, p_h16, p_oatt);
        // o = relu(o_att @ Wo + bo)   [16384, 512]
        gemm_split_kernel<<<dim3(8, 128, 1), 256, GEMM_SMEM, s_main>>>(p_oatt, Wo, bo, o_out, nullptr, 512, 512, 1);
    }
    cudaEventRecord(ev_main, s_main);

    // join back to the capture stream
    cudaStreamWaitEvent(0, ev_main, 0);
}

// round 12
// speedup vs baseline: 1.0655x; 1.0655x over previous
#include <cuda_runtime.h>
#include <cuda_bf16.h>
#include <cuda_fp16.h>
#include <mma.h>
#include <cstdint>

using namespace nvcuda;

static constexpr int BATCH = 4;
static constexpr int NTOK  = 4096;   // H*W
static constexpr int CH    = 512;
static constexpr int FGD   = 64;

static constexpr long long O_ELEMS = (long long)BATCH * NTOK * CH;    // 8388608
static constexpr long long B_ELEMS = (long long)BATCH * NTOK * NTOK;  // 67108864

// ---------------- scratch (static __device__ -- no allocations allowed) ----------
__device__ float  d_f[(size_t)BATCH * NTOK * FGD];
__device__ float  d_g[(size_t)BATCH * NTOK * FGD];
__device__ __half d_h16[(size_t)BATCH * NTOK * CH];          // h in fp16 (h >= 0)
__device__ __half d_betah[(size_t)BATCH * NTOK * NTOK];      // beta in fp16
__device__ float  d_oatt[(size_t)BATCH * NTOK * CH];
__device__ float  d_rowm[BATCH * NTOK];
__device__ float  d_rowl[BATCH * NTOK];
__device__ float  d_beta_scratch[(size_t)BATCH * NTOK * NTOK]; // only if harness wants o-only

// ---------------- bf16 split helper (x = hi + lo, ~17-bit effective mantissa) ----
__device__ __forceinline__ void split4(const float4 v, __nv_bfloat16* hi, __nv_bfloat16* lo) {
    hi[0] = __float2bfloat16(v.x); lo[0] = __float2bfloat16(v.x - __bfloat162float(hi[0]));
    hi[1] = __float2bfloat16(v.y); lo[1] = __float2bfloat16(v.y - __bfloat162float(hi[1]));
    hi[2] = __float2bfloat16(v.z); lo[2] = __float2bfloat16(v.z - __bfloat162float(hi[2]));
    hi[3] = __float2bfloat16(v.w); lo[3] = __float2bfloat16(v.w - __bfloat162float(hi[3]));
}

// ---------------- cp.async helpers (Ampere path, valid on sm_103) ----------------
__device__ __forceinline__ uint32_t smem_u32(const void* p) {
    uint32_t a;
    asm("{ .reg .u64 t; cvta.to.shared.u64 t, %1; cvt.u32.u64 %0, t; }" : "=r"(a) : "l"(p));
    return a;
}
__device__ __forceinline__ void cp_async16(uint32_t dst, const void* src) {
    asm volatile("cp.async.cg.shared.global [%0], [%1], 16;" :: "r"(dst), "l"(src));
}
__device__ __forceinline__ void cp_commit() {
    asm volatile("cp.async.commit_group;");
}
template <int N>
__device__ __forceinline__ void cp_wait() {
    asm volatile("cp.async.wait_group %0;" :: "n"(N));
}

// ================== generic GEMM v2: C = act(A[M,K] @ B[K,N] + bias) ==============
static constexpr int GBM = 128, GBN = 64, GBK = 32;
static constexpr int ALD = GBK + 8;   // 40
static constexpr int BLD = GBN + 8;   // 72
static constexpr int CLD = GBN + 4;   // 68
static constexpr int G_AHALF = GBM * ALD;              // 5120
static constexpr int G_BHALF = GBK * BLD;              // 2304
static constexpr int G_STAGE = 2 * G_AHALF + 2 * G_BHALF;   // 14848 bf16
static constexpr int GEMM_SMEM = 2 * G_STAGE * 2;      // 59392 B

__global__ void __launch_bounds__(256)
gemm_split_kernel(const float* __restrict__ A, const float* __restrict__ B,
                  const float* __restrict__ bias, float* __restrict__ C,
                  __half* __restrict__ C16,
                  int K, int N, int relu)
{
    extern __shared__ __align__(16) unsigned char gsm[];
    float* Csm = reinterpret_cast<float*>(gsm);

    const int m0  = blockIdx.y * GBM;
    const int n0  = blockIdx.x * GBN;
    const int tid = threadIdx.x;
    const int wid = tid >> 5;
    const int wm  = wid >> 1;
    const int wn  = wid & 1;

    wmma::fragment<wmma::accumulator, 16, 16, 16, float> acc[2][2];
    #pragma unroll
    for (int i = 0; i < 2; i++)
        #pragma unroll
        for (int j = 0; j < 2; j++)
            wmma::fill_fragment(acc[i][j], 0.0f);

    const int NCHUNK = K >> 5;
    float4 ra[4], rb[2];

    #pragma unroll
    for (int i = 0; i < 4; i++) {
        int idx = tid + i * 256;
        int row = idx >> 3;
        int c4  = (idx & 7) << 2;
        ra[i] = *reinterpret_cast<const float4*>(A + (long long)(m0 + row) * K + c4);
    }
    #pragma unroll
    for (int i = 0; i < 2; i++) {
        int idx = tid + i * 256;
        int row = idx >> 4;
        int c4  = (idx & 15) << 2;
        rb[i] = *reinterpret_cast<const float4*>(B + (long long)row * N + n0 + c4);
    }

    #pragma unroll 1
    for (int c = 0; c < NCHUNK; c++) {
        __nv_bfloat16* stage = reinterpret_cast<__nv_bfloat16*>(gsm) + (c & 1) * G_STAGE;
        __nv_bfloat16* Ahi = stage;
        __nv_bfloat16* Alo = Ahi + G_AHALF;
        __nv_bfloat16* Bhi = Alo + G_AHALF;
        __nv_bfloat16* Blo = Bhi + G_BHALF;

        #pragma unroll
        for (int i = 0; i < 4; i++) {
            int idx = tid + i * 256;
            int row = idx >> 3;
            int c4  = (idx & 7) << 2;
            split4(ra[i], &Ahi[row * ALD + c4], &Alo[row * ALD + c4]);
        }
        #pragma unroll
        for (int i = 0; i < 2; i++) {
            int idx = tid + i * 256;
            int row = idx >> 4;
            int c4  = (idx & 15) << 2;
            split4(rb[i], &Bhi[row * BLD + c4], &Blo[row * BLD + c4]);
        }
        __syncthreads();

        if (c + 1 < NCHUNK) {
            const long long k0 = (long long)(c + 1) << 5;
            #pragma unroll
            for (int i = 0; i < 4; i++) {
                int idx = tid + i * 256;
                int row = idx >> 3;
                int c4  = (idx & 7) << 2;
                ra[i] = *reinterpret_cast<const float4*>(A + (long long)(m0 + row) * K + k0 + c4);
            }
            #pragma unroll
            for (int i = 0; i < 2; i++) {
                int idx = tid + i * 256;
                int row = idx >> 4;
                int c4  = (idx & 15) << 2;
                rb[i] = *reinterpret_cast<const float4*>(B + (k0 + row) * N + n0 + c4);
            }
        }

        #pragma unroll
        for (int ks = 0; ks < 2; ks++) {
            wmma::fragment<wmma::matrix_a, 16, 16, 16, __nv_bfloat16, wmma::row_major> ah[2], al[2];
            wmma::fragment<wmma::matrix_b, 16, 16, 16, __nv_bfloat16, wmma::row_major> bh[2], bl[2];
            #pragma unroll
            for (int r2 = 0; r2 < 2; r2++) {
                wmma::load_matrix_sync(ah[r2], &Ahi[(wm * 32 + r2 * 16) * ALD + ks * 16], ALD);
                wmma::load_matrix_sync(al[r2], &Alo[(wm * 32 + r2 * 16) * ALD + ks * 16], ALD);
            }
            #pragma unroll
            for (int cn = 0; cn < 2; cn++) {
                wmma::load_matrix_sync(bh[cn], &Bhi[(ks * 16) * BLD + wn * 32 + cn * 16], BLD);
                wmma::load_matrix_sync(bl[cn], &Blo[(ks * 16) * BLD + wn * 32 + cn * 16], BLD);
            }
            #pragma unroll
            for (int r2 = 0; r2 < 2; r2++)
                #pragma unroll
                for (int cn = 0; cn < 2; cn++) {
                    wmma::mma_sync(acc[r2][cn], ah[r2], bh[cn], acc[r2][cn]);
                    wmma::mma_sync(acc[r2][cn], ah[r2], bl[cn], acc[r2][cn]);
                    wmma::mma_sync(acc[r2][cn], al[r2], bh[cn], acc[r2][cn]);
                }
        }
    }

    __syncthreads();
    #pragma unroll
    for (int r2 = 0; r2 < 2; r2++)
        #pragma unroll
        for (int cn = 0; cn < 2; cn++)
            wmma::store_matrix_sync(&Csm[(wm * 32 + r2 * 16) * CLD + wn * 32 + cn * 16],
                                    acc[r2][cn], CLD, wmma::mem_row_major);
    __syncthreads();

    #pragma unroll
    for (int i = 0; i < 8; i++) {
        int idx = tid + i * 256;
        int row = idx >> 4;
        int c4  = (idx & 15) << 2;
        float4 v = *reinterpret_cast<const float4*>(&Csm[row * CLD + c4]);
        if (bias != nullptr) {
            float4 bv = *reinterpret_cast<const float4*>(bias + n0 + c4);
            v.x += bv.x; v.y += bv.y; v.z += bv.z; v.w += bv.w;
        }
        if (relu) {
            v.x = fmaxf(v.x, 0.f); v.y = fmaxf(v.y, 0.f);
            v.z = fmaxf(v.z, 0.f); v.w = fmaxf(v.w, 0.f);
        }
        if (C16 != nullptr) {
            __half2 h01 = __floats2half2_rn(v.x, v.y);
            __half2 h23 = __floats2half2_rn(v.z, v.w);
            uint2 p;
            p.x = *reinterpret_cast<uint32_t*>(&h01);
            p.y = *reinterpret_cast<uint32_t*>(&h23);
            *reinterpret_cast<uint2*>(C16 + (long long)(m0 + row) * N + n0 + c4) = p;
        } else {
            *reinterpret_cast<float4*>(C + (long long)(m0 + row) * N + n0 + c4) = v;
        }
    }
}

// ================== PV GEMM v4 (proven best): 128x64, KC=64, cp.async ============
static constexpr int PALD = 72;
static constexpr int PBLD = 72;
static constexpr int PV_ABUF = 128 * PALD;
static constexpr int PV_BBUF = 64 * PBLD;
static constexpr int PV_STAGE = PV_ABUF + PV_BBUF;  // 13824 halves
static constexpr int PV_SMEM = 2 * PV_STAGE * 2;    // 55296 B
static constexpr int PV_NCHUNK = NTOK / 64;         // 64

__global__ void __launch_bounds__(256)
pv_f16s_kernel(const __half* __restrict__ betah, const __half* __restrict__ h16,
               float* __restrict__ oatt)
{
    extern __shared__ __align__(16) __half pvsm[];

    const __half* A = betah + (long long)blockIdx.z * NTOK * NTOK;
    const __half* B = h16   + (long long)blockIdx.z * NTOK * CH;
    float*        C = oatt  + (long long)blockIdx.z * NTOK * CH;
    const int m0  = blockIdx.y * 128;
    const int n0  = blockIdx.x * 64;
    const int tid = threadIdx.x;
    const int wid = tid >> 5;
    const int wm  = wid >> 1;
    const int wn  = wid & 1;

    const uint32_t smbase = smem_u32(pvsm);

    auto issue_chunk = [&](int c) {
        const int buf = c & 1;
        uint32_t sa = smbase + (uint32_t)(buf * PV_STAGE) * 2;
        uint32_t sb = sa + (uint32_t)PV_ABUF * 2;
        const long long k0 = (long long)c * 64;
        #pragma unroll
        for (int i = 0; i < 4; i++) {
            int idx = tid + i * 256;
            int row = idx >> 3;
            int c8  = (idx & 7) << 3;
            cp_async16(sa + (uint32_t)(row * PALD + c8) * 2,
                       A + (long long)(m0 + row) * NTOK + k0 + c8);
        }
        #pragma unroll
        for (int i = 0; i < 2; i++) {
            int idx = tid + i * 256;
            int row = idx >> 3;
            int c8  = (idx & 7) << 3;
            cp_async16(sb + (uint32_t)(row * PBLD + c8) * 2,
                       B + (long long)(k0 + row) * CH + n0 + c8);
        }
        cp_commit();
    };

    wmma::fragment<wmma::accumulator, 16, 16, 16, float> acc[2][2];
    #pragma unroll
    for (int i = 0; i < 2; i++)
        #pragma unroll
        for (int j = 0; j < 2; j++)
            wmma::fill_fragment(acc[i][j], 0.0f);

    issue_chunk(0);

    #pragma unroll 1
    for (int c = 0; c < PV_NCHUNK; c++) {
        if (c + 1 < PV_NCHUNK) {
            issue_chunk(c + 1);
            cp_wait<1>();
        } else {
            cp_wait<0>();
        }
        __syncthreads();

        const __half* Af = pvsm + (c & 1) * PV_STAGE;
        const __half* Bf = Af + PV_ABUF;
        #pragma unroll
        for (int ks = 0; ks < 4; ks++) {
            wmma::fragment<wmma::matrix_a, 16, 16, 16, __half, wmma::row_major> af[2];
            wmma::fragment<wmma::matrix_b, 16, 16, 16, __half, wmma::row_major> bf[2];
            #pragma unroll
            for (int r2 = 0; r2 < 2; r2++)
                wmma::load_matrix_sync(af[r2], &Af[(wm * 32 + r2 * 16) * PALD + ks * 16], PALD);
            #pragma unroll
            for (int cn = 0; cn < 2; cn++)
                wmma::load_matrix_sync(bf[cn], &Bf[(ks * 16) * PBLD + wn * 32 + cn * 16], PBLD);
            #pragma unroll
            for (int r2 = 0; r2 < 2; r2++)
                #pragma unroll
                for (int cn = 0; cn < 2; cn++)
                    wmma::mma_sync(acc[r2][cn], af[r2], bf[cn], acc[r2][cn]);
        }
        __syncthreads();
    }

    #pragma unroll
    for (int r2 = 0; r2 < 2; r2++)
        #pragma unroll
        for (int cn = 0; cn < 2; cn++)
            wmma::store_matrix_sync(C + (long long)(m0 + wm * 32 + r2 * 16) * CH + n0 + wn * 32 + cn * 16,
                                    acc[r2][cn], CH, wmma::mem_row_major);
}

// ======== scores v2: 64-row query tiles, 256 threads, 2 CTAs/SM ==================
// S = g @ f^T (raw) streamed to gmem + online row max/sumexp.
static constexpr int SLD = 132;
static constexpr int GLD = 72;
// Ghi/Glo 64*GLD bf16 each, Fhi/Flo 128*GLD bf16 each, S 64*SLD fp32
static constexpr int SCORES_SMEM = (2 * 64 * GLD + 2 * 128 * GLD) * 2 + 64 * SLD * 4; // 89088 B

__global__ void __launch_bounds__(256, 2)
scores_kernel(const float* __restrict__ g, const float* __restrict__ f,
              float* __restrict__ sraw, float* __restrict__ rowm, float* __restrict__ rowl)
{
    extern __shared__ unsigned char smraw[];
    __nv_bfloat16* Ghi = reinterpret_cast<__nv_bfloat16*>(smraw);
    __nv_bfloat16* Glo = Ghi + 64 * GLD;
    __nv_bfloat16* Fhi = Glo + 64 * GLD;
    __nv_bfloat16* Flo = Fhi + 128 * GLD;
    float*         S   = reinterpret_cast<float*>(Flo + 128 * GLD);

    const int b   = blockIdx.y;
    const int r0  = blockIdx.x * 64;
    const int tid = threadIdx.x;
    const int wid = tid >> 5;
    const int wm  = wid >> 2;  // 0..1 -> S rows 32*wm
    const int wn  = wid & 3;   // 0..3 -> S cols 32*wn

    const float* gbase = g + ((long long)b * NTOK + r0) * FGD;
    const float* fbase = f + (long long)b * NTOK * FGD;

    // stage g block [64 x 64] once
    #pragma unroll
    for (int i = 0; i < 4; i++) {
        int idx = tid + i * 256;           // 0..1023
        int row = idx >> 4;                // 0..63
        int c4  = (idx & 15) << 2;
        float4 v = *reinterpret_cast<const float4*>(gbase + row * FGD + c4);
        split4(v, &Ghi[row * GLD + c4], &Glo[row * GLD + c4]);
    }

    float m_run = -1e30f, l_run = 0.0f;
    const int srow = tid >> 2;             // 0..63
    const int q    = tid & 3;
    const float4* Sscan4 = reinterpret_cast<const float4*>(&S[srow * SLD + q * 32]);

    for (int ci = 0; ci < 32; ci++) {
        __syncthreads();   // protect F/S from previous chunk (covers G on ci==0)
        #pragma unroll
        for (int i = 0; i < 8; i++) {
            int idx = tid + i * 256;       // 0..2047
            int row = idx >> 4;            // 0..127
            int c4  = (idx & 15) << 2;
            float4 v = *reinterpret_cast<const float4*>(fbase + (long long)(ci * 128 + row) * FGD + c4);
            split4(v, &Fhi[row * GLD + c4], &Flo[row * GLD + c4]);
        }
        __syncthreads();

        wmma::fragment<wmma::accumulator, 16, 16, 16, float> acc[2][2];
        #pragma unroll
        for (int i = 0; i < 2; i++)
            #pragma unroll
            for (int j = 0; j < 2; j++)
                wmma::fill_fragment(acc[i][j], 0.0f);

        #pragma unroll
        for (int ks = 0; ks < 4; ks++) {
            wmma::fragment<wmma::matrix_a, 16, 16, 16, __nv_bfloat16, wmma::row_major> ah[2], al[2];
            wmma::fragment<wmma::matrix_b, 16, 16, 16, __nv_bfloat16, wmma::col_major> bh[2], bl[2];
            #pragma unroll
            for (int r2 = 0; r2 < 2; r2++) {
                wmma::load_matrix_sync(ah[r2], &Ghi[(wm * 32 + r2 * 16) * GLD + ks * 16], GLD);
                wmma::load_matrix_sync(al[r2], &Glo[(wm * 32 + r2 * 16) * GLD + ks * 16], GLD);
            }
            #pragma unroll
            for (int cn = 0; cn < 2; cn++) {
                wmma::load_matrix_sync(bh[cn], &Fhi[(wn * 32 + cn * 16) * GLD + ks * 16], GLD);
                wmma::load_matrix_sync(bl[cn], &Flo[(wn * 32 + cn * 16) * GLD + ks * 16], GLD);
            }
            #pragma unroll
            for (int r2 = 0; r2 < 2; r2++)
                #pragma unroll
                for (int cn = 0; cn < 2; cn++) {
                    wmma::mma_sync(acc[r2][cn], ah[r2], bh[cn], acc[r2][cn]);
                    wmma::mma_sync(acc[r2][cn], ah[r2], bl[cn], acc[r2][cn]);
                    wmma::mma_sync(acc[r2][cn], al[r2], bh[cn], acc[r2][cn]);
                }
        }
        #pragma unroll
        for (int r2 = 0; r2 < 2; r2++)
            #pragma unroll
            for (int cn = 0; cn < 2; cn++)
                wmma::store_matrix_sync(&S[(wm * 32 + r2 * 16) * SLD + wn * 32 + cn * 16],
                                        acc[r2][cn], SLD, wmma::mem_row_major);
        __syncthreads();

        size_t gout = (size_t)(b * NTOK + r0) * NTOK + (size_t)ci * 128;
        #pragma unroll
        for (int i = 0; i < 8; i++) {
            int idx = tid + i * 256;       // 0..2047
            int row = idx >> 5;            // 0..63
            int c4  = (idx & 31) << 2;     // 0..124
            float4 v = *reinterpret_cast<const float4*>(&S[row * SLD + c4]);
            *reinterpret_cast<float4*>(sraw + gout + (size_t)row * NTOK + c4) = v;
        }
        float vmax = -1e30f;
        #pragma unroll
        for (int j = 0; j < 8; j++) {
            float4 a = Sscan4[j];
            vmax = fmaxf(vmax, fmaxf(fmaxf(a.x, a.y), fmaxf(a.z, a.w)));
        }
        float mn = fmaxf(m_run, vmax);
        float add = 0.0f;
        #pragma unroll
        for (int j = 0; j < 8; j++) {
            float4 a = Sscan4[j];
            add += __expf(a.x - mn) + __expf(a.y - mn) + __expf(a.z - mn) + __expf(a.w - mn);
        }
        l_run = l_run * __expf(m_run - mn) + add;
        m_run = mn;
    }

    #pragma unroll
    for (int off = 1; off < 4; off <<= 1) {
        float mo  = __shfl_xor_sync(0xffffffffu, m_run, off);
        float lo2 = __shfl_xor_sync(0xffffffffu, l_run, off);
        float mn  = fmaxf(m_run, mo);
        l_run = l_run * __expf(m_run - mn) + lo2 * __expf(mo - mn);
        m_run = mn;
    }
    if (q == 0) {
        rowm[b * NTOK + r0 + srow] = m_run;
        rowl[b * NTOK + r0 + srow] = l_run;
    }
}

// ============ normalize: beta = exp(s - m)/l  (fp32 out + fp16 copy) =============
__global__ void __launch_bounds__(256)
normalize_kernel(float* __restrict__ beta, __half* __restrict__ betah,
                 const float* __restrict__ rowm, const float* __restrict__ rowl)
{
    long long idx = (long long)blockIdx.x * 256 + threadIdx.x;
    if (idx >= (B_ELEMS >> 2)) return;
    int rowg = (int)(idx >> 10);
    float m   = __ldg(rowm + rowg);
    float inv = 1.0f / __ldg(rowl + rowg);
    float4 v = *reinterpret_cast<float4*>(beta + idx * 4);
    v.x = __expf(v.x - m) * inv;
    v.y = __expf(v.y - m) * inv;
    v.z = __expf(v.z - m) * inv;
    v.w = __expf(v.w - m) * inv;
    *reinterpret_cast<float4*>(beta + idx * 4) = v;
    __half2 h01 = __floats2half2_rn(v.x, v.y);
    __half2 h23 = __floats2half2_rn(v.z, v.w);
    uint2 p;
    p.x = *reinterpret_cast<uint32_t*>(&h01);
    p.y = *reinterpret_cast<uint32_t*>(&h23);
    *reinterpret_cast<uint2*>(betah + idx * 4) = p;
}

// ================== launch ========================================================
extern "C" void kernel_launch(void* const* d_in, const int* in_sizes, int n_in,
                              void* d_out, int out_size)
{
    (void)in_sizes; (void)n_in;
    const float* l  = (const float*)d_in[0];
    const float* r  = (const float*)d_in[1];
    const float* Wf = (const float*)d_in[2];
    const float* Wg = (const float*)d_in[3];
    const float* Wh = (const float*)d_in[4];
    const float* Wo = (const float*)d_in[5];
    const float* bf = (const float*)d_in[6];
    const float* bg = (const float*)d_in[7];
    const float* bh = (const float*)d_in[8];
    const float* bo = (const float*)d_in[9];
    float* out = (float*)d_out;

    float  *p_f, *p_g, *p_oatt, *p_rowm, *p_rowl, *p_bscr;
    __half *p_h16, *p_betah;
    cudaGetSymbolAddress((void**)&p_f,     d_f);
    cudaGetSymbolAddress((void**)&p_g,     d_g);
    cudaGetSymbolAddress((void**)&p_h16,   d_h16);
    cudaGetSymbolAddress((void**)&p_betah, d_betah);
    cudaGetSymbolAddress((void**)&p_oatt,  d_oatt);
    cudaGetSymbolAddress((void**)&p_rowm,  d_rowm);
    cudaGetSymbolAddress((void**)&p_rowl,  d_rowl);
    cudaGetSymbolAddress((void**)&p_bscr,  d_beta_scratch);

    // output layout: reference returns (o, beta) -> o first, then beta
    float* o_out    = nullptr;
    float* beta_out = nullptr;
    long long osz = (long long)out_size;
    if (osz >= O_ELEMS + B_ELEMS) { o_out = out; beta_out = out + O_ELEMS; }
    else if (osz == B_ELEMS)      { beta_out = out; }
    else                          { o_out = out; beta_out = p_bscr; }

    // one-time setup (first call is the non-captured correctness run)
    static cudaStream_t s_main = nullptr, s_side = nullptr, s_aux = nullptr;
    static cudaEvent_t  ev_root = nullptr, ev_side = nullptr, ev_aux = nullptr, ev_main = nullptr;
    if (s_main == nullptr) {
        cudaStreamCreateWithFlags(&s_main, cudaStreamNonBlocking);
        cudaStreamCreateWithFlags(&s_side, cudaStreamNonBlocking);
        cudaStreamCreateWithFlags(&s_aux,  cudaStreamNonBlocking);
        cudaEventCreateWithFlags(&ev_root, cudaEventDisableTiming);
        cudaEventCreateWithFlags(&ev_side, cudaEventDisableTiming);
        cudaEventCreateWithFlags(&ev_aux,  cudaEventDisableTiming);
        cudaEventCreateWithFlags(&ev_main, cudaEventDisableTiming);
        cudaFuncSetAttribute(scores_kernel, cudaFuncAttributeMaxDynamicSharedMemorySize, SCORES_SMEM);
        cudaFuncSetAttribute(pv_f16s_kernel, cudaFuncAttributeMaxDynamicSharedMemorySize, PV_SMEM);
        cudaFuncSetAttribute(gemm_split_kernel, cudaFuncAttributeMaxDynamicSharedMemorySize, GEMM_SMEM);
    }

    // fork from the capture (default) stream
    cudaEventRecord(ev_root, 0);
    cudaStreamWaitEvent(s_main, ev_root, 0);
    cudaStreamWaitEvent(s_side, ev_root, 0);
    cudaStreamWaitEvent(s_aux,  ev_root, 0);

    // side stream: h = relu(l @ Wh + bh) as fp16 (only needed by PV)
    gemm_split_kernel<<<dim3(8, 128, 1), 256, GEMM_SMEM, s_side>>>(l, Wh, bh, nullptr, p_h16, 512, 512, 1);
    cudaEventRecord(ev_side, s_side);

    // aux stream: f ; main stream: g  (concurrent, both feed scores)
    gemm_split_kernel<<<dim3(1, 128, 1), 256, GEMM_SMEM, s_aux>>>(l, Wf, bf, p_f, nullptr, 512, 64, 1);
    cudaEventRecord(ev_aux, s_aux);
    gemm_split_kernel<<<dim3(1, 128, 1), 256, GEMM_SMEM, s_main>>>(r, Wg, bg, p_g, nullptr, 512, 64, 1);
    cudaStreamWaitEvent(s_main, ev_aux, 0);

    // main: scores -> normalize
    scores_kernel<<<dim3(64, 4, 1), 256, SCORES_SMEM, s_main>>>(p_g, p_f, beta_out, p_rowm, p_rowl);
    normalize_kernel<<<65536, 256, 0, s_main>>>(beta_out, p_betah, p_rowm, p_rowl);

    // join h before PV
    cudaStreamWaitEvent(s_main, ev_side, 0);
    if (o_out) {
        // o_att = beta @ h  (per batch) -- v4 PV (128x64, KC=64, cp.async)
        pv_f16s_kernel<<<dim3(8, 32, 4), 256, PV_SMEM, s_main>>>(p_betah, p_h16, p_oatt);
        // o = relu(o_att @ Wo + bo)   [16384, 512]
        gemm_split_kernel<<<dim3(8, 128, 1), 256, GEMM_SMEM, s_main>>>(p_oatt, Wo, bo, o_out, nullptr, 512, 512, 1);
    }
    cudaEventRecord(ev_main, s_main);

    // join back to the capture stream
    cudaStreamWaitEvent(0, ev_main, 0);
}